// round 8
// baseline (speedup 1.0000x reference)
#include <cuda_runtime.h>
#include <cuda_fp16.h>
#include <math.h>
#include <stdint.h>

// Problem constants
#define L_SEQ   2048
#define DM      1024
#define DI      1024
#define DTR     64
#define DS      16
#define PROJ    (DTR + 2 * DI * DS)   // 32832
#define NPAD    32896                 // 257 * 128
#define KDIM    1024

// -------- scratch (static device globals; no allocation) --------
__device__ __half g_dbch[(size_t)L_SEQ * PROJ];     // B/C as fp16 (cols 0..63 unused)
__device__ float  g_dlr[(size_t)L_SEQ * DTR];       // exact fp32 delta_lr
__device__ float  g_delta[(size_t)L_SEQ * DI];
__device__ __half g_xf[(size_t)L_SEQ * DM];
__device__ __half g_wf[(size_t)NPAD * DM];
__device__ __half g_wof[(size_t)DM * DI];
__device__ __half g_yf[(size_t)L_SEQ * DI];

// ============================================================================
// helpers
// ============================================================================
__device__ __forceinline__ uint32_t smem_u32(const void* p) {
    uint32_t a;
    asm("{ .reg .u64 t; cvta.to.shared.u64 t, %1; cvt.u32.u64 %0, t; }" : "=r"(a) : "l"(p));
    return a;
}
__device__ __forceinline__ uint32_t swz128(uint32_t o) { return o ^ ((o >> 3) & 0x70); }

__device__ __forceinline__ void cp_async16(uint32_t dst, const void* src) {
    asm volatile("cp.async.cg.shared.global [%0], [%1], 16;" :: "r"(dst), "l"(src));
}
#define CP_COMMIT() asm volatile("cp.async.commit_group;" ::: "memory")
#define CP_WAIT(n)  asm volatile("cp.async.wait_group %0;" :: "n"(n) : "memory")

__device__ __forceinline__ void ldsm4(uint32_t* r, uint32_t addr) {
    asm volatile("ldmatrix.sync.aligned.m8n8.x4.shared.b16 {%0,%1,%2,%3}, [%4];"
        : "=r"(r[0]), "=r"(r[1]), "=r"(r[2]), "=r"(r[3]) : "r"(addr));
}
__device__ __forceinline__ void mma_f16(float* d, const uint32_t* a, const uint32_t* b) {
    asm volatile(
        "mma.sync.aligned.m16n8k16.row.col.f32.f16.f16.f32 "
        "{%0,%1,%2,%3}, {%4,%5,%6,%7}, {%8,%9}, {%0,%1,%2,%3};"
        : "+f"(d[0]), "+f"(d[1]), "+f"(d[2]), "+f"(d[3])
        : "r"(a[0]), "r"(a[1]), "r"(a[2]), "r"(a[3]), "r"(b[0]), "r"(b[1]));
}

// ============================================================================
// fp32 -> fp16 conversion (zero-pad beyond n_valid)
// ============================================================================
__global__ __launch_bounds__(256) void cvt16_kernel(
    const float* __restrict__ src, __half* __restrict__ dst,
    size_t n_valid, size_t n_total)
{
    size_t i = ((size_t)blockIdx.x * 256 + threadIdx.x) * 4;
    if (i >= n_total) return;
    float4 v = make_float4(0.f, 0.f, 0.f, 0.f);
    if (i < n_valid) v = *(const float4*)(src + i);
    *(__half2*)(dst + i)     = __floats2half2_rn(v.x, v.y);
    *(__half2*)(dst + i + 2) = __floats2half2_rn(v.z, v.w);
}

// ============================================================================
// FP16 GEMM: C[m,n] = A[m,:]·B[n,:]  (f32 accumulate)
// CTA 128x128, BK=64, 256 threads (8 warps 2x4, warp tile 64x32),
// 3-stage cp.async pipeline (32 KB/stage), 16 k-iters.
// Templated epilogue: OT = __half (dbc) or float (final out).
// ============================================================================
#define F_ATILE  16384              // 128 rows x 128 B
#define F_STAGE  32768
#define F_NSTAGE 3
#define SMEM_F16_TOTAL (F_NSTAGE * F_STAGE)   // 96 KB
#define F_NKC    (KDIM / 64)        // 16

template<typename OT>
__global__ __launch_bounds__(256, 2) void gemm_f16(
    const __half* __restrict__ A, const __half* __restrict__ B,
    OT* __restrict__ C, int ldc, int nvalid)
{
    extern __shared__ char smem[];
    const uint32_t sbase = smem_u32(smem);
    const int tid = threadIdx.x;
    const int wid = tid >> 5, lane = tid & 31;
    const int wm = wid & 1, wn = wid >> 1;       // 2 (m) x 4 (n)

    const int m0 = blockIdx.x * 128;
    const int n0 = blockIdx.y * 128;

    float acc[4][4][4];
    #pragma unroll
    for (int i = 0; i < 4; i++)
        #pragma unroll
        for (int j = 0; j < 4; j++)
            #pragma unroll
            for (int q = 0; q < 4; q++) acc[i][j][q] = 0.f;

    auto issue = [&](int kc) {
        if (kc < F_NKC) {
            const uint32_t soff = sbase + (kc % F_NSTAGE) * F_STAGE;
            #pragma unroll
            for (int j = 0; j < 4; j++) {
                const int q = tid * 4 + j;          // 0..1023
                const int row = q >> 3, c = q & 7;
                const uint32_t so = swz128((uint32_t)(row * 128 + c * 16));
                const size_t ga = (size_t)(m0 + row) * KDIM + (size_t)kc * 64 + c * 8;
                const size_t gb = (size_t)(n0 + row) * KDIM + (size_t)kc * 64 + c * 8;
                cp_async16(soff + so, A + ga);
                cp_async16(soff + F_ATILE + so, B + gb);
            }
        }
        CP_COMMIT();
    };

    issue(0);
    issue(1);

    #pragma unroll 1
    for (int kc = 0; kc < F_NKC; kc++) {
        if (kc + 1 < F_NKC) CP_WAIT(1); else CP_WAIT(0);
        __syncthreads();
        issue(kc + 2);

        const uint32_t sA = sbase + (kc % F_NSTAGE) * F_STAGE;

        #pragma unroll
        for (int ks = 0; ks < 4; ks++) {
            uint32_t bf[4][2];
            #pragma unroll
            for (int p = 0; p < 2; p++) {
                const int rowb = wn * 32 + p * 16 + ((lane >> 4) << 3) + (lane & 7);
                const int chb  = ks * 2 + ((lane >> 3) & 1);
                const uint32_t ob = swz128((uint32_t)(rowb * 128 + chb * 16));
                ldsm4(&bf[p * 2][0], sA + F_ATILE + ob);
            }
            #pragma unroll
            for (int mf = 0; mf < 4; mf++) {
                const int rowa = wm * 64 + mf * 16 + (lane & 15);
                const int cha  = ks * 2 + (lane >> 4);
                const uint32_t oa = swz128((uint32_t)(rowa * 128 + cha * 16));
                uint32_t af[4];
                ldsm4(af, sA + oa);
                #pragma unroll
                for (int nf = 0; nf < 4; nf++) mma_f16(acc[mf][nf], af, bf[nf]);
            }
        }
    }

    const int g = lane >> 2, t4 = lane & 3;
    #pragma unroll
    for (int mf = 0; mf < 4; mf++) {
        #pragma unroll
        for (int nf = 0; nf < 4; nf++) {
            const int m = m0 + wm * 64 + mf * 16 + g;
            const int n = n0 + wn * 32 + nf * 8 + t4 * 2;
            if (n < nvalid) {
                if constexpr (sizeof(OT) == 2) {
                    *(__half2*)((__half*)C + (size_t)m * ldc + n) =
                        __floats2half2_rn(acc[mf][nf][0], acc[mf][nf][1]);
                    *(__half2*)((__half*)C + (size_t)(m + 8) * ldc + n) =
                        __floats2half2_rn(acc[mf][nf][2], acc[mf][nf][3]);
                } else {
                    *(float2*)((float*)C + (size_t)m * ldc + n) =
                        make_float2(acc[mf][nf][0], acc[mf][nf][1]);
                    *(float2*)((float*)C + (size_t)(m + 8) * ldc + n) =
                        make_float2(acc[mf][nf][2], acc[mf][nf][3]);
                }
            }
        }
    }
}

// ============================================================================
// Exact fp32 delta_lr: dlr[t,k] = x[t,:]·W_in[k,:]  (t=2048, k=64, K=1024)
// Block: 256 threads (64 k x 4 t-groups), 32 t-rows/block, smem-tiled.
// ============================================================================
__global__ __launch_bounds__(256) void dlr_kernel(
    const float* __restrict__ x, const float* __restrict__ W_in)
{
    __shared__ float sx[64][36];      // [kk][t] transposed, padded
    __shared__ float sw[64][65];      // [kk][k] transposed, padded
    const int tid = threadIdx.x;
    const int k = tid & 63;
    const int tg = tid >> 6;          // 0..3 (8 t-rows each)
    const int t0 = blockIdx.x * 32;

    float acc[8];
    #pragma unroll
    for (int i = 0; i < 8; i++) acc[i] = 0.f;

    for (int kc = 0; kc < 16; kc++) {
        // load x tile: 32 t x 64 kk (512 float4 chunks, 2 per thread), transpose
        #pragma unroll
        for (int j = 0; j < 2; j++) {
            const int q = tid * 2 + j;        // 0..511
            const int t = q >> 4, c = q & 15;
            float4 v = *(const float4*)(x + (size_t)(t0 + t) * KDIM + kc * 64 + c * 4);
            sx[c * 4 + 0][t] = v.x; sx[c * 4 + 1][t] = v.y;
            sx[c * 4 + 2][t] = v.z; sx[c * 4 + 3][t] = v.w;
        }
        // load W tile: 64 k x 64 kk (1024 chunks, 4 per thread), transpose
        #pragma unroll
        for (int j = 0; j < 4; j++) {
            const int q = tid * 4 + j;        // 0..1023
            const int k2 = q >> 4, c = q & 15;
            float4 v = *(const float4*)(W_in + (size_t)k2 * KDIM + kc * 64 + c * 4);
            sw[c * 4 + 0][k2] = v.x; sw[c * 4 + 1][k2] = v.y;
            sw[c * 4 + 2][k2] = v.z; sw[c * 4 + 3][k2] = v.w;
        }
        __syncthreads();
        #pragma unroll 16
        for (int kk = 0; kk < 64; kk++) {
            const float w = sw[kk][k];
            #pragma unroll
            for (int i = 0; i < 8; i++)
                acc[i] = fmaf(sx[kk][tg * 8 + i], w, acc[i]);
        }
        __syncthreads();
    }
    #pragma unroll
    for (int i = 0; i < 8; i++)
        g_dlr[(size_t)(t0 + tg * 8 + i) * DTR + k] = acc[i];
}

// ============================================================================
// delta[t,d] = softplus(g_dlr[t,:] · W_delta[d,:])
// ============================================================================
__global__ __launch_bounds__(128) void delta_kernel(const float* __restrict__ W_delta)
{
    __shared__ float s_dl[8][64];
    __shared__ float s_wT[64][129];
    const int tid = threadIdx.x;
    const int t0 = blockIdx.x * 8;
    const int d0 = blockIdx.y * 128;

    for (int i = tid; i < 8 * 64; i += 128) {
        int t = i >> 6, kk = i & 63;
        s_dl[t][kk] = g_dlr[(size_t)(t0 + t) * DTR + kk];
    }
    for (int i = tid; i < 128 * 64; i += 128) {
        int d = i >> 6, kk = i & 63;
        s_wT[kk][d] = W_delta[(size_t)(d0 + d) * DTR + kk];
    }
    __syncthreads();

    float accv[8];
    #pragma unroll
    for (int t = 0; t < 8; t++) accv[t] = 0.f;
    #pragma unroll 8
    for (int kk = 0; kk < 64; kk++) {
        float w = s_wT[kk][tid];
        #pragma unroll
        for (int t = 0; t < 8; t++) accv[t] = fmaf(s_dl[t][kk], w, accv[t]);
    }
    #pragma unroll
    for (int t = 0; t < 8; t++) {
        float z = accv[t];
        float sp = fmaxf(z, 0.f) + log1pf(__expf(-fabsf(z)));
        g_delta[(size_t)(t0 + t) * DI + d0 + tid] = sp;
    }
}

// ============================================================================
// Selective scan: 1 thread per (d, s). 128 blocks x 128 threads, prefetch 8.
// Reads B/C as fp16; writes y as fp16 for the output GEMM.
// ============================================================================
__global__ __launch_bounds__(128) void scan_kernel(
    const float* __restrict__ x, const float* __restrict__ A_log,
    const float* __restrict__ Dv)
{
    const int g = blockIdx.x * 128 + threadIdx.x;
    const int d = g >> 4, s = g & 15;
    const float a = -expf(A_log[d * DS + s]);
    const float Dd = Dv[d];
    const __half* bp = g_dbch + DTR + d * DS + s;
    const __half* cp = bp + DI * DS;

    float Bpf[8], Cpf[8], Tpf[8], Xpf[8];
    #pragma unroll
    for (int i = 0; i < 8; i++) {
        Bpf[i] = __half2float(bp[(size_t)i * PROJ]);
        Cpf[i] = __half2float(cp[(size_t)i * PROJ]);
        Tpf[i] = g_delta[(size_t)i * DI + d];
        Xpf[i] = x[(size_t)i * DI + d];
    }
    float h = 0.f;
    #pragma unroll 8
    for (int t = 0; t < L_SEQ; t++) {
        const int sl = t & 7;
        const float dt = Tpf[sl], xt = Xpf[sl], Bv = Bpf[sl], Cv = Cpf[sl];
        const int tn = t + 8;
        if (tn < L_SEQ) {
            Bpf[sl] = __half2float(bp[(size_t)tn * PROJ]);
            Cpf[sl] = __half2float(cp[(size_t)tn * PROJ]);
            Tpf[sl] = g_delta[(size_t)tn * DI + d];
            Xpf[sl] = x[(size_t)tn * DI + d];
        }
        h = fmaf(__expf(dt * a), h, dt * xt * Bv);
        float yv = h * Cv;
        yv += __shfl_xor_sync(0xffffffffu, yv, 1);
        yv += __shfl_xor_sync(0xffffffffu, yv, 2);
        yv += __shfl_xor_sync(0xffffffffu, yv, 4);
        yv += __shfl_xor_sync(0xffffffffu, yv, 8);
        if (s == 0)
            g_yf[(size_t)t * DI + d] = __float2half_rn(fmaf(xt, Dd, yv));
    }
}

// ============================================================================
// Launch
// ============================================================================
extern "C" void kernel_launch(void* const* d_in, const int* in_sizes, int n_in,
                              void* d_out, int out_size)
{
    const float* x       = (const float*)d_in[0];
    const float* W_in    = (const float*)d_in[1];
    const float* W_delta = (const float*)d_in[2];
    const float* A_log   = (const float*)d_in[3];
    const float* Dv      = (const float*)d_in[4];
    const float* W_out   = (const float*)d_in[5];
    float* out = (float*)d_out;

    __half *dbch, *xf, *wf, *wof, *yf;
    cudaGetSymbolAddress((void**)&dbch, g_dbch);
    cudaGetSymbolAddress((void**)&xf, g_xf);
    cudaGetSymbolAddress((void**)&wf, g_wf);
    cudaGetSymbolAddress((void**)&wof, g_wof);
    cudaGetSymbolAddress((void**)&yf, g_yf);

    cudaFuncSetAttribute(gemm_f16<__half>, cudaFuncAttributeMaxDynamicSharedMemorySize,
                         SMEM_F16_TOTAL);
    cudaFuncSetAttribute(gemm_f16<float>, cudaFuncAttributeMaxDynamicSharedMemorySize,
                         SMEM_F16_TOTAL);

    // 1) conversions
    {
        size_t nx = (size_t)L_SEQ * DM;
        cvt16_kernel<<<(unsigned)((nx / 4 + 255) / 256), 256>>>(x, xf, nx, nx);
        size_t nwv = (size_t)PROJ * DM, nwt = (size_t)NPAD * DM;
        cvt16_kernel<<<(unsigned)((nwt / 4 + 255) / 256), 256>>>(W_in, wf, nwv, nwt);
        size_t nwo = (size_t)DM * DI;
        cvt16_kernel<<<(unsigned)((nwo / 4 + 255) / 256), 256>>>(W_out, wof, nwo, nwo);
    }
    // 2) dbc (B/C) = x @ W_in^T  -> fp16 output
    {
        dim3 grid(L_SEQ / 128, NPAD / 128);   // 16 x 257
        gemm_f16<__half><<<grid, 256, SMEM_F16_TOTAL>>>(xf, wf, dbch, PROJ, PROJ);
    }
    // 3) exact fp32 delta_lr
    dlr_kernel<<<L_SEQ / 32, 256>>>(x, W_in);
    // 4) delta
    {
        dim3 grid(L_SEQ / 8, DI / 128);
        delta_kernel<<<grid, 128>>>(W_delta);
    }
    // 5) scan (fp16 B/C in, fp16 y out)
    scan_kernel<<<128, 128>>>(x, A_log, Dv);
    // 6) out = y @ W_out^T  -> f32 output
    {
        dim3 grid(L_SEQ / 128, DM / 128);     // 16 x 8
        gemm_f16<float><<<grid, 256, SMEM_F16_TOTAL>>>(yf, wof, out, DM, DM);
    }
}

// round 9
// speedup vs baseline: 1.2986x; 1.2986x over previous
#include <cuda_runtime.h>
#include <cuda_fp16.h>
#include <math.h>
#include <stdint.h>

// Problem constants
#define L_SEQ   2048
#define DM      1024
#define DI      1024
#define DTR     64
#define DS      16
#define PROJ    (DTR + 2 * DI * DS)   // 32832
#define NPAD    32896                 // 257 * 128
#define KDIM    1024

// -------- scratch (static device globals; no allocation) --------
__device__ __half g_dbch[(size_t)L_SEQ * PROJ];     // B/C as fp16 (cols 0..63 unused)
__device__ float  g_dlr[(size_t)L_SEQ * DTR];       // exact fp32 delta_lr
__device__ float  g_delta[(size_t)L_SEQ * DI];
__device__ __half g_xf[(size_t)L_SEQ * DM];
__device__ __half g_wf[(size_t)NPAD * DM];
__device__ __half g_wof[(size_t)DM * DI];
__device__ __half g_yf[(size_t)L_SEQ * DI];

// ============================================================================
// helpers
// ============================================================================
__device__ __forceinline__ uint32_t smem_u32(const void* p) {
    uint32_t a;
    asm("{ .reg .u64 t; cvta.to.shared.u64 t, %1; cvt.u32.u64 %0, t; }" : "=r"(a) : "l"(p));
    return a;
}
__device__ __forceinline__ uint32_t swz128(uint32_t o) { return o ^ ((o >> 3) & 0x70); }

__device__ __forceinline__ void cp_async16(uint32_t dst, const void* src) {
    asm volatile("cp.async.cg.shared.global [%0], [%1], 16;" :: "r"(dst), "l"(src));
}
#define CP_COMMIT() asm volatile("cp.async.commit_group;" ::: "memory")
#define CP_WAIT(n)  asm volatile("cp.async.wait_group %0;" :: "n"(n) : "memory")

__device__ __forceinline__ void ldsm4(uint32_t* r, uint32_t addr) {
    asm volatile("ldmatrix.sync.aligned.m8n8.x4.shared.b16 {%0,%1,%2,%3}, [%4];"
        : "=r"(r[0]), "=r"(r[1]), "=r"(r[2]), "=r"(r[3]) : "r"(addr));
}
__device__ __forceinline__ void mma_f16(float* d, const uint32_t* a, const uint32_t* b) {
    asm volatile(
        "mma.sync.aligned.m16n8k16.row.col.f32.f16.f16.f32 "
        "{%0,%1,%2,%3}, {%4,%5,%6,%7}, {%8,%9}, {%0,%1,%2,%3};"
        : "+f"(d[0]), "+f"(d[1]), "+f"(d[2]), "+f"(d[3])
        : "r"(a[0]), "r"(a[1]), "r"(a[2]), "r"(a[3]), "r"(b[0]), "r"(b[1]));
}

// ============================================================================
// fp32 -> fp16 conversion (zero-pad beyond n_valid)
// ============================================================================
__global__ __launch_bounds__(256) void cvt16_kernel(
    const float* __restrict__ src, __half* __restrict__ dst,
    size_t n_valid, size_t n_total)
{
    size_t i = ((size_t)blockIdx.x * 256 + threadIdx.x) * 4;
    if (i >= n_total) return;
    float4 v = make_float4(0.f, 0.f, 0.f, 0.f);
    if (i < n_valid) v = *(const float4*)(src + i);
    *(__half2*)(dst + i)     = __floats2half2_rn(v.x, v.y);
    *(__half2*)(dst + i + 2) = __floats2half2_rn(v.z, v.w);
}

// ============================================================================
// FP16 GEMM: C[m,n] = A[m,:]·B[n,:]  (f32 accumulate)
// CTA 128x128, BK=64, 256 threads (8 warps 2x4, warp tile 64x32),
// 3-stage cp.async pipeline. Templated epilogue.
// ============================================================================
#define F_ATILE  16384
#define F_STAGE  32768
#define F_NSTAGE 3
#define SMEM_F16_TOTAL (F_NSTAGE * F_STAGE)   // 96 KB
#define F_NKC    (KDIM / 64)        // 16

template<typename OT>
__global__ __launch_bounds__(256, 2) void gemm_f16(
    const __half* __restrict__ A, const __half* __restrict__ B,
    OT* __restrict__ C, int ldc, int nvalid)
{
    extern __shared__ char smem[];
    const uint32_t sbase = smem_u32(smem);
    const int tid = threadIdx.x;
    const int wid = tid >> 5, lane = tid & 31;
    const int wm = wid & 1, wn = wid >> 1;

    const int m0 = blockIdx.x * 128;
    const int n0 = blockIdx.y * 128;

    float acc[4][4][4];
    #pragma unroll
    for (int i = 0; i < 4; i++)
        #pragma unroll
        for (int j = 0; j < 4; j++)
            #pragma unroll
            for (int q = 0; q < 4; q++) acc[i][j][q] = 0.f;

    auto issue = [&](int kc) {
        if (kc < F_NKC) {
            const uint32_t soff = sbase + (kc % F_NSTAGE) * F_STAGE;
            #pragma unroll
            for (int j = 0; j < 4; j++) {
                const int q = tid * 4 + j;
                const int row = q >> 3, c = q & 7;
                const uint32_t so = swz128((uint32_t)(row * 128 + c * 16));
                const size_t ga = (size_t)(m0 + row) * KDIM + (size_t)kc * 64 + c * 8;
                const size_t gb = (size_t)(n0 + row) * KDIM + (size_t)kc * 64 + c * 8;
                cp_async16(soff + so, A + ga);
                cp_async16(soff + F_ATILE + so, B + gb);
            }
        }
        CP_COMMIT();
    };

    issue(0);
    issue(1);

    #pragma unroll 1
    for (int kc = 0; kc < F_NKC; kc++) {
        if (kc + 1 < F_NKC) CP_WAIT(1); else CP_WAIT(0);
        __syncthreads();
        issue(kc + 2);

        const uint32_t sA = sbase + (kc % F_NSTAGE) * F_STAGE;

        #pragma unroll
        for (int ks = 0; ks < 4; ks++) {
            uint32_t bf[4][2];
            #pragma unroll
            for (int p = 0; p < 2; p++) {
                const int rowb = wn * 32 + p * 16 + ((lane >> 4) << 3) + (lane & 7);
                const int chb  = ks * 2 + ((lane >> 3) & 1);
                const uint32_t ob = swz128((uint32_t)(rowb * 128 + chb * 16));
                ldsm4(&bf[p * 2][0], sA + F_ATILE + ob);
            }
            #pragma unroll
            for (int mf = 0; mf < 4; mf++) {
                const int rowa = wm * 64 + mf * 16 + (lane & 15);
                const int cha  = ks * 2 + (lane >> 4);
                const uint32_t oa = swz128((uint32_t)(rowa * 128 + cha * 16));
                uint32_t af[4];
                ldsm4(af, sA + oa);
                #pragma unroll
                for (int nf = 0; nf < 4; nf++) mma_f16(acc[mf][nf], af, bf[nf]);
            }
        }
    }

    const int g = lane >> 2, t4 = lane & 3;
    #pragma unroll
    for (int mf = 0; mf < 4; mf++) {
        #pragma unroll
        for (int nf = 0; nf < 4; nf++) {
            const int m = m0 + wm * 64 + mf * 16 + g;
            const int n = n0 + wn * 32 + nf * 8 + t4 * 2;
            if (n < nvalid) {
                if constexpr (sizeof(OT) == 2) {
                    *(__half2*)((__half*)C + (size_t)m * ldc + n) =
                        __floats2half2_rn(acc[mf][nf][0], acc[mf][nf][1]);
                    *(__half2*)((__half*)C + (size_t)(m + 8) * ldc + n) =
                        __floats2half2_rn(acc[mf][nf][2], acc[mf][nf][3]);
                } else {
                    *(float2*)((float*)C + (size_t)m * ldc + n) =
                        make_float2(acc[mf][nf][0], acc[mf][nf][1]);
                    *(float2*)((float*)C + (size_t)(m + 8) * ldc + n) =
                        make_float2(acc[mf][nf][2], acc[mf][nf][3]);
                }
            }
        }
    }
}

// ============================================================================
// Exact fp32 delta_lr: dlr[t,k] = x[t,:]·W_in[k,:]
// ============================================================================
__global__ __launch_bounds__(256) void dlr_kernel(
    const float* __restrict__ x, const float* __restrict__ W_in)
{
    __shared__ float sx[64][36];
    __shared__ float sw[64][65];
    const int tid = threadIdx.x;
    const int k = tid & 63;
    const int tg = tid >> 6;
    const int t0 = blockIdx.x * 32;

    float acc[8];
    #pragma unroll
    for (int i = 0; i < 8; i++) acc[i] = 0.f;

    for (int kc = 0; kc < 16; kc++) {
        #pragma unroll
        for (int j = 0; j < 2; j++) {
            const int q = tid * 2 + j;
            const int t = q >> 4, c = q & 15;
            float4 v = *(const float4*)(x + (size_t)(t0 + t) * KDIM + kc * 64 + c * 4);
            sx[c * 4 + 0][t] = v.x; sx[c * 4 + 1][t] = v.y;
            sx[c * 4 + 2][t] = v.z; sx[c * 4 + 3][t] = v.w;
        }
        #pragma unroll
        for (int j = 0; j < 4; j++) {
            const int q = tid * 4 + j;
            const int k2 = q >> 4, c = q & 15;
            float4 v = *(const float4*)(W_in + (size_t)k2 * KDIM + kc * 64 + c * 4);
            sw[c * 4 + 0][k2] = v.x; sw[c * 4 + 1][k2] = v.y;
            sw[c * 4 + 2][k2] = v.z; sw[c * 4 + 3][k2] = v.w;
        }
        __syncthreads();
        #pragma unroll 16
        for (int kk = 0; kk < 64; kk++) {
            const float w = sw[kk][k];
            #pragma unroll
            for (int i = 0; i < 8; i++)
                acc[i] = fmaf(sx[kk][tg * 8 + i], w, acc[i]);
        }
        __syncthreads();
    }
    #pragma unroll
    for (int i = 0; i < 8; i++)
        g_dlr[(size_t)(t0 + tg * 8 + i) * DTR + k] = acc[i];
}

// ============================================================================
// delta[t,d] = softplus(g_dlr[t,:] · W_delta[d,:])
// ============================================================================
__global__ __launch_bounds__(128) void delta_kernel(const float* __restrict__ W_delta)
{
    __shared__ float s_dl[8][64];
    __shared__ float s_wT[64][129];
    const int tid = threadIdx.x;
    const int t0 = blockIdx.x * 8;
    const int d0 = blockIdx.y * 128;

    for (int i = tid; i < 8 * 64; i += 128) {
        int t = i >> 6, kk = i & 63;
        s_dl[t][kk] = g_dlr[(size_t)(t0 + t) * DTR + kk];
    }
    for (int i = tid; i < 128 * 64; i += 128) {
        int d = i >> 6, kk = i & 63;
        s_wT[kk][d] = W_delta[(size_t)(d0 + d) * DTR + kk];
    }
    __syncthreads();

    float accv[8];
    #pragma unroll
    for (int t = 0; t < 8; t++) accv[t] = 0.f;
    #pragma unroll 8
    for (int kk = 0; kk < 64; kk++) {
        float w = s_wT[kk][tid];
        #pragma unroll
        for (int t = 0; t < 8; t++) accv[t] = fmaf(s_dl[t][kk], w, accv[t]);
    }
    #pragma unroll
    for (int t = 0; t < 8; t++) {
        float z = accv[t];
        float sp = fmaxf(z, 0.f) + log1pf(__expf(-fabsf(z)));
        g_delta[(size_t)(t0 + t) * DI + d0 + tid] = sp;
    }
}

// ============================================================================
// Selective scan v2: cp.async smem-staged, 32-step chunks, 4-stage ring.
// 128 CTAs x 128 threads; CTA owns 8 channels (thread = (lc, s)).
// Per step, CTA's B (and C) slice is 256 B contiguous in g_dbch.
// ============================================================================
#define SC_T      32                          // steps per chunk
#define SC_NCH    (L_SEQ / SC_T)              // 64 chunks
#define SC_BBYTES (SC_T * 256)                // 8192
#define SC_DBYTES (SC_T * 32)                 // 1024
#define SC_B_OFF  0
#define SC_C_OFF  SC_BBYTES
#define SC_D_OFF  (2 * SC_BBYTES)
#define SC_X_OFF  (2 * SC_BBYTES + SC_DBYTES)
#define SC_STAGE  (2 * SC_BBYTES + 2 * SC_DBYTES)   // 18432
#define SC_NSTAGE 4
#define SMEM_SCAN_TOTAL (SC_NSTAGE * SC_STAGE)      // 73728

__global__ __launch_bounds__(128) void scan_kernel(
    const float* __restrict__ x, const float* __restrict__ A_log,
    const float* __restrict__ Dv)
{
    extern __shared__ char smem[];
    const uint32_t sbase = smem_u32(smem);
    const int tid = threadIdx.x;
    const int blk = blockIdx.x;
    const int lc = tid >> 4, s = tid & 15;     // local channel 0..7, state 0..15
    const int d = blk * 8 + lc;

    const float a = -expf(A_log[d * DS + s]);
    const float Dd = Dv[d];

    // global bases for this CTA's contiguous per-step slices
    const char* gB = (const char*)(g_dbch + DTR + (size_t)blk * 128);
    const char* gC = (const char*)(g_dbch + DTR + DI * DS + (size_t)blk * 128);
    const char* gD = (const char*)(g_delta + (size_t)blk * 8);
    const char* gX = (const char*)(x + (size_t)blk * 8);

    auto issue = [&](int ch) {
        if (ch < SC_NCH) {
            const uint32_t soff = sbase + (ch & 3) * SC_STAGE;
            const size_t t0 = (size_t)ch * SC_T;
            // B and C: 512 cp16 each? -> 16 per step; thread does 4 of each
            #pragma unroll
            for (int j = 0; j < 4; j++) {
                const int q = tid * 4 + j;           // 0..511
                const int st = q >> 4, off = (q & 15) * 16;
                cp_async16(soff + SC_B_OFF + st * 256 + off,
                           gB + (t0 + st) * (PROJ * 2) + off);
                cp_async16(soff + SC_C_OFF + st * 256 + off,
                           gC + (t0 + st) * (PROJ * 2) + off);
            }
            // delta + x: 64 cp16 each (2 per step)
            {
                const int q = tid & 63;              // 0..63
                const int st = q >> 1, off = (q & 1) * 16;
                if (tid < 64)
                    cp_async16(soff + SC_D_OFF + st * 32 + off,
                               gD + (t0 + st) * (DI * 4) + off);
                else
                    cp_async16(soff + SC_X_OFF + st * 32 + off,
                               gX + (t0 + st) * (DI * 4) + off);
            }
        }
        CP_COMMIT();
    };

    issue(0); issue(1); issue(2);

    float h = 0.f;
    #pragma unroll 1
    for (int ch = 0; ch < SC_NCH; ch++) {
        CP_WAIT(2);
        __syncthreads();
        issue(ch + 3);

        const uint32_t soff = sbase + (ch & 3) * SC_STAGE;
        const __half* sB = (const __half*)(smem + (soff - sbase) + SC_B_OFF);
        const __half* sC = (const __half*)(smem + (soff - sbase) + SC_C_OFF);
        const float* sD  = (const float*)(smem + (soff - sbase) + SC_D_OFF);
        const float* sX  = (const float*)(smem + (soff - sbase) + SC_X_OFF);
        const int tbase = ch * SC_T;

        #pragma unroll 8
        for (int st = 0; st < SC_T; st++) {
            const float Bv = __half2float(sB[st * 128 + tid]);
            const float Cv = __half2float(sC[st * 128 + tid]);
            const float dt = sD[st * 8 + lc];
            const float xt = sX[st * 8 + lc];
            h = fmaf(__expf(dt * a), h, dt * xt * Bv);
            float yv = h * Cv;
            yv += __shfl_xor_sync(0xffffffffu, yv, 1);
            yv += __shfl_xor_sync(0xffffffffu, yv, 2);
            yv += __shfl_xor_sync(0xffffffffu, yv, 4);
            yv += __shfl_xor_sync(0xffffffffu, yv, 8);
            if (s == 0)
                g_yf[(size_t)(tbase + st) * DI + d] =
                    __float2half_rn(fmaf(xt, Dd, yv));
        }
    }
}

// ============================================================================
// Launch
// ============================================================================
extern "C" void kernel_launch(void* const* d_in, const int* in_sizes, int n_in,
                              void* d_out, int out_size)
{
    const float* x       = (const float*)d_in[0];
    const float* W_in    = (const float*)d_in[1];
    const float* W_delta = (const float*)d_in[2];
    const float* A_log   = (const float*)d_in[3];
    const float* Dv      = (const float*)d_in[4];
    const float* W_out   = (const float*)d_in[5];
    float* out = (float*)d_out;

    __half *dbch, *xf, *wf, *wof, *yf;
    cudaGetSymbolAddress((void**)&dbch, g_dbch);
    cudaGetSymbolAddress((void**)&xf, g_xf);
    cudaGetSymbolAddress((void**)&wf, g_wf);
    cudaGetSymbolAddress((void**)&wof, g_wof);
    cudaGetSymbolAddress((void**)&yf, g_yf);

    cudaFuncSetAttribute(gemm_f16<__half>, cudaFuncAttributeMaxDynamicSharedMemorySize,
                         SMEM_F16_TOTAL);
    cudaFuncSetAttribute(gemm_f16<float>, cudaFuncAttributeMaxDynamicSharedMemorySize,
                         SMEM_F16_TOTAL);
    cudaFuncSetAttribute(scan_kernel, cudaFuncAttributeMaxDynamicSharedMemorySize,
                         SMEM_SCAN_TOTAL);

    // 1) conversions
    {
        size_t nx = (size_t)L_SEQ * DM;
        cvt16_kernel<<<(unsigned)((nx / 4 + 255) / 256), 256>>>(x, xf, nx, nx);
        size_t nwv = (size_t)PROJ * DM, nwt = (size_t)NPAD * DM;
        cvt16_kernel<<<(unsigned)((nwt / 4 + 255) / 256), 256>>>(W_in, wf, nwv, nwt);
        size_t nwo = (size_t)DM * DI;
        cvt16_kernel<<<(unsigned)((nwo / 4 + 255) / 256), 256>>>(W_out, wof, nwo, nwo);
    }
    // 2) dbc (B/C) = x @ W_in^T  -> fp16 output
    {
        dim3 grid(L_SEQ / 128, NPAD / 128);
        gemm_f16<__half><<<grid, 256, SMEM_F16_TOTAL>>>(xf, wf, dbch, PROJ, PROJ);
    }
    // 3) exact fp32 delta_lr
    dlr_kernel<<<L_SEQ / 32, 256>>>(x, W_in);
    // 4) delta
    {
        dim3 grid(L_SEQ / 8, DI / 128);
        delta_kernel<<<grid, 128>>>(W_delta);
    }
    // 5) scan v2 (smem-staged)
    scan_kernel<<<128, 128, SMEM_SCAN_TOTAL>>>(x, A_log, Dv);
    // 6) out = y @ W_out^T  -> f32 output
    {
        dim3 grid(L_SEQ / 128, DM / 128);
        gemm_f16<float><<<grid, 256, SMEM_F16_TOTAL>>>(yf, wof, out, DM, DM);
    }
}